// round 1
// baseline (speedup 1.0000x reference)
#include <cuda_runtime.h>

#define NQ   4
#define DIM  16
#define SPB  16      // samples per block
#define IMG  576     // floats per sample
#define SS   584     // padded sample stride in smem (floats); 584 % 32 == 8 -> disjoint banks per sample pair
#define BN_EPS 1e-5f

// scratch (static device globals; no allocation)
__device__ float g_partials[16384 * 8];
__device__ float g_scale[4];
__device__ float g_shift[4];

// Composed CNOT ring permutation for one layer: out[i] = in[P[i]]
// P = p1 ∘ p2 ∘ p3 ∘ p4 applied as state[:,perm] sequentially (verified vs reference).
__device__ __forceinline__ void apply_cnot_ring(float sx[16], float sy[16]) {
    constexpr int P[16] = {0, 13, 3, 14, 6, 11, 5, 8, 12, 1, 15, 2, 10, 7, 9, 4};
    float tx[16], ty[16];
#pragma unroll
    for (int i = 0; i < 16; i++) { tx[i] = sx[i]; ty[i] = sy[i]; }
#pragma unroll
    for (int i = 0; i < 16; i++) { sx[i] = tx[P[i]]; sy[i] = ty[P[i]]; }
}

__global__ void __launch_bounds__(256) k_main(
    const float* __restrict__ x,
    const float* __restrict__ enc_w,   // (4,16)
    const float* __restrict__ enc_b,   // (4,)
    const float* __restrict__ qp,      // (2,4)
    float* __restrict__ zout,          // (B,4)
    int B)
{
    __shared__ float xs[SPB * SS];        // 37376 B
    __shared__ float pooled[SPB][17];     // padded

    const int t   = threadIdx.x;
    const int blk = blockIdx.x;

    // ---- stage 16 images into smem, coalesced float4 ----
    const float4* xg = (const float4*)(x + (size_t)blk * SPB * IMG);
#pragma unroll
    for (int k = 0; k < 9; k++) {
        int i4 = t + k * 256;             // 0..2303
        int s  = i4 / 144;                // 144 float4 per sample
        int w  = i4 - s * 144;
        *(float4*)(xs + s * SS + w * 4) = xg[i4];
    }
    __syncthreads();

    // ---- 6x6 average pooling: thread t -> (sample t/16, bin t%16) ----
    {
        int s  = t >> 4, b = t & 15;
        int rb = b >> 2, cb = b & 3;
        const float* bp = xs + s * SS + rb * 6 * 24 + cb * 6;
        float acc = 0.f;
#pragma unroll
        for (int dr = 0; dr < 6; dr++) {
            const float2* p2 = (const float2*)(bp + dr * 24);
            float2 a = p2[0], c = p2[1], d = p2[2];
            acc += (a.x + a.y) + (c.x + c.y) + (d.x + d.y);
        }
        pooled[s][b] = acc * (1.0f / 36.0f);
    }
    __syncthreads();

    // ---- per-sample encoder + quantum circuit (threads 0..15) ----
    float z0 = 0.f, z1 = 0.f, z2 = 0.f, z3 = 0.f;
    if (t < SPB) {
        float enc[NQ];
#pragma unroll
        for (int k = 0; k < NQ; k++) {
            float a = __ldg(enc_b + k);
#pragma unroll
            for (int i = 0; i < 16; i++)
                a += pooled[t][i] * __ldg(enc_w + k * 16 + i);
            enc[k] = a;
        }

        float sx[16], sy[16];
#pragma unroll
        for (int i = 0; i < 16; i++) { sx[i] = 0.f; sy[i] = 0.f; }
        sx[0] = 1.f;

#pragma unroll
        for (int layer = 0; layer < 2; layer++) {
#pragma unroll
            for (int q = 0; q < NQ; q++) {
                const int st = 8 >> q;  // bit value of qubit q (q0 = MSB)
                // RY(enc[q])
                float c, sn;
                sincosf(0.5f * enc[q], &sn, &c);
#pragma unroll
                for (int i = 0; i < 16; i++) {
                    if ((i & st) == 0) {
                        const int j = i | st;
                        float ax = sx[i], ay = sy[i];
                        float bx = sx[j], by = sy[j];
                        sx[i] = c * ax - sn * bx;  sy[i] = c * ay - sn * by;
                        sx[j] = sn * ax + c * bx;  sy[j] = sn * ay + c * by;
                    }
                }
                // RZ(q_params[layer][q]): bit0 *= e^{-i h}, bit1 *= e^{+i h}
                float hc, hs;
                sincosf(0.5f * __ldg(qp + layer * NQ + q), &hs, &hc);
#pragma unroll
                for (int i = 0; i < 16; i++) {
                    float xx = sx[i], yy = sy[i];
                    if (i & st) { sx[i] = xx * hc - yy * hs;  sy[i] = yy * hc + xx * hs; }
                    else        { sx[i] = xx * hc + yy * hs;  sy[i] = yy * hc - xx * hs; }
                }
            }
            apply_cnot_ring(sx, sy);
        }

        // Z expectations
#pragma unroll
        for (int i = 0; i < 16; i++) {
            float p = sx[i] * sx[i] + sy[i] * sy[i];
            z0 += ((i >> 3) & 1) ? -p : p;
            z1 += ((i >> 2) & 1) ? -p : p;
            z2 += ((i >> 1) & 1) ? -p : p;
            z3 += ( i       & 1) ? -p : p;
        }

        float4 zz = make_float4(z0, z1, z2, z3);
        *(float4*)(zout + (size_t)(blk * SPB + t) * 4) = zz;
    }

    // ---- deterministic per-block (sum, sumsq) via warp-0 shuffle reduce ----
    if (t < 32) {
        float v[8] = {z0, z1, z2, z3, z0 * z0, z1 * z1, z2 * z2, z3 * z3};
#pragma unroll
        for (int off = 16; off >= 1; off >>= 1) {
#pragma unroll
            for (int j = 0; j < 8; j++)
                v[j] += __shfl_xor_sync(0xffffffffu, v[j], off);
        }
        if (t == 0) {
#pragma unroll
            for (int j = 0; j < 8; j++)
                g_partials[(size_t)blk * 8 + j] = v[j];
        }
    }
}

__global__ void k_stats(const float* __restrict__ bnw,
                        const float* __restrict__ bnb,
                        int nblk, int B)
{
    __shared__ float s[256];
    const int t    = threadIdx.x;
    const int stat = t & 7;
    const int g    = t >> 3;   // 32 groups per stat
    float acc = 0.f;
    for (int i = g; i < nblk; i += 32)
        acc += g_partials[(size_t)i * 8 + stat];
    s[t] = acc;
    __syncthreads();
#pragma unroll
    for (int off = 128; off >= 8; off >>= 1) {
        if (t < off) s[t] += s[t + off];
        __syncthreads();
    }
    if (t < 4) {
        float invB = 1.0f / (float)B;
        float mean = s[t] * invB;
        float var  = s[4 + t] * invB - mean * mean;
        float inv  = rsqrtf(var + BN_EPS);
        float sc   = inv * __ldg(bnw + t);
        g_scale[t] = sc;
        g_shift[t] = __ldg(bnb + t) - mean * sc;
    }
}

__global__ void k_norm(float* __restrict__ zout, int B)
{
    int i = blockIdx.x * blockDim.x + threadIdx.x;
    if (i < B) {
        float4 z = ((float4*)zout)[i];
        z.x = z.x * g_scale[0] + g_shift[0];
        z.y = z.y * g_scale[1] + g_shift[1];
        z.z = z.z * g_scale[2] + g_shift[2];
        z.w = z.w * g_scale[3] + g_shift[3];
        ((float4*)zout)[i] = z;
    }
}

extern "C" void kernel_launch(void* const* d_in, const int* in_sizes, int n_in,
                              void* d_out, int out_size)
{
    const float* x     = (const float*)d_in[0];
    const float* enc_w = (const float*)d_in[1];
    const float* enc_b = (const float*)d_in[2];
    const float* qp    = (const float*)d_in[3];
    const float* bnw   = (const float*)d_in[4];
    const float* bnb   = (const float*)d_in[5];
    float* out = (float*)d_out;

    int B    = in_sizes[0] / IMG;   // 131072
    int nblk = B / SPB;             // 8192

    k_main<<<nblk, 256>>>(x, enc_w, enc_b, qp, out, B);
    k_stats<<<1, 256>>>(bnw, bnb, nblk, B);
    k_norm<<<(B + 255) / 256, 256>>>(out, B);
}

// round 2
// speedup vs baseline: 1.2198x; 1.2198x over previous
#include <cuda_runtime.h>

#define NQ   4
#define DIM  16
#define SPB  16      // samples per block in pool kernel
#define IMG  576     // floats per sample
#define SS   584     // padded sample stride in smem
#define BN_EPS 1e-5f
#define BMAX 131072

// static scratch (no allocation)
__device__ float g_pooled[BMAX * 16];
__device__ float g_partials[1024 * 8];
__device__ float g_scale[4];
__device__ float g_shift[4];

// ---------------- pooling kernel: pure streaming ----------------
__global__ void __launch_bounds__(256) k_pool(const float* __restrict__ x)
{
    __shared__ float xs[SPB * SS];   // 37376 B

    const int t   = threadIdx.x;
    const int blk = blockIdx.x;

    const float4* xg = (const float4*)(x + (size_t)blk * SPB * IMG);
#pragma unroll
    for (int k = 0; k < 9; k++) {
        int i4 = t + k * 256;             // 0..2303 ; 144 float4 per sample
        int s  = i4 / 144;
        int w  = i4 - s * 144;
        *(float4*)(xs + s * SS + w * 4) = xg[i4];
    }
    __syncthreads();

    // thread t -> (sample t/16, bin t%16); write coalesced to global
    int s  = t >> 4, b = t & 15;
    int rb = b >> 2, cb = b & 3;
    const float* bp = xs + s * SS + rb * 6 * 24 + cb * 6;
    float acc = 0.f;
#pragma unroll
    for (int dr = 0; dr < 6; dr++) {
        const float2* p2 = (const float2*)(bp + dr * 24);
        float2 a = p2[0], c = p2[1], d = p2[2];
        acc += (a.x + a.y) + (c.x + c.y) + (d.x + d.y);
    }
    g_pooled[(size_t)blk * 256 + t] = acc * (1.0f / 36.0f);
}

// ---------------- circuit kernel: one sample per thread ----------------
__global__ void __launch_bounds__(256, 2) k_circuit(
    const float* __restrict__ enc_w,   // (4,16)
    const float* __restrict__ enc_b,   // (4,)
    const float* __restrict__ qp,      // (2,4)
    float* __restrict__ zout)          // (B,4)
{
    const int t   = threadIdx.x;
    const int gid = blockIdx.x * 256 + t;

    // load pooled features (16 floats)
    float pl[16];
    const float4* pp = (const float4*)(g_pooled + (size_t)gid * 16);
#pragma unroll
    for (int k = 0; k < 4; k++) {
        float4 v = pp[k];
        pl[4 * k] = v.x; pl[4 * k + 1] = v.y; pl[4 * k + 2] = v.z; pl[4 * k + 3] = v.w;
    }

    // encoder (weights broadcast via uniform ldg)
    float enc[NQ];
#pragma unroll
    for (int k = 0; k < NQ; k++) {
        float a = __ldg(enc_b + k);
#pragma unroll
        for (int i = 0; i < 16; i++)
            a += pl[i] * __ldg(enc_w + k * 16 + i);
        enc[k] = a;
    }

    // statevector in registers
    float sx[16], sy[16];
#pragma unroll
    for (int i = 0; i < 16; i++) { sx[i] = 0.f; sy[i] = 0.f; }
    sx[0] = 1.f;

#pragma unroll
    for (int layer = 0; layer < 2; layer++) {
#pragma unroll
        for (int q = 0; q < NQ; q++) {
            const int st = 8 >> q;
            float c, sn;
            sincosf(0.5f * enc[q], &sn, &c);
#pragma unroll
            for (int i = 0; i < 16; i++) {
                if ((i & st) == 0) {
                    const int j = i | st;
                    float ax = sx[i], ay = sy[i];
                    float bx = sx[j], by = sy[j];
                    sx[i] = c * ax - sn * bx;  sy[i] = c * ay - sn * by;
                    sx[j] = sn * ax + c * bx;  sy[j] = sn * ay + c * by;
                }
            }
            float hc, hs;
            sincosf(0.5f * __ldg(qp + layer * NQ + q), &hs, &hc);
#pragma unroll
            for (int i = 0; i < 16; i++) {
                float xx = sx[i], yy = sy[i];
                if (i & st) { sx[i] = xx * hc - yy * hs;  sy[i] = yy * hc + xx * hs; }
                else        { sx[i] = xx * hc + yy * hs;  sy[i] = yy * hc - xx * hs; }
            }
        }
        // composed CNOT ring permutation (compile-time register rename)
        {
            constexpr int P[16] = {0, 13, 3, 14, 6, 11, 5, 8, 12, 1, 15, 2, 10, 7, 9, 4};
            float tx[16], ty[16];
#pragma unroll
            for (int i = 0; i < 16; i++) { tx[i] = sx[i]; ty[i] = sy[i]; }
#pragma unroll
            for (int i = 0; i < 16; i++) { sx[i] = tx[P[i]]; sy[i] = ty[P[i]]; }
        }
    }

    float z0 = 0.f, z1 = 0.f, z2 = 0.f, z3 = 0.f;
#pragma unroll
    for (int i = 0; i < 16; i++) {
        float p = sx[i] * sx[i] + sy[i] * sy[i];
        z0 += ((i >> 3) & 1) ? -p : p;
        z1 += ((i >> 2) & 1) ? -p : p;
        z2 += ((i >> 1) & 1) ? -p : p;
        z3 += ( i       & 1) ? -p : p;
    }

    *(float4*)(zout + (size_t)gid * 4) = make_float4(z0, z1, z2, z3);

    // deterministic block-level (sum, sumsq): warp shuffle then smem tree
    float v[8] = {z0, z1, z2, z3, z0 * z0, z1 * z1, z2 * z2, z3 * z3};
#pragma unroll
    for (int off = 16; off >= 1; off >>= 1)
#pragma unroll
        for (int j = 0; j < 8; j++)
            v[j] += __shfl_xor_sync(0xffffffffu, v[j], off);

    __shared__ float sred[8][8];
    const int wid = t >> 5, lid = t & 31;
    if (lid == 0)
#pragma unroll
        for (int j = 0; j < 8; j++) sred[wid][j] = v[j];
    __syncthreads();
    if (t < 8) {
        float a = 0.f;
#pragma unroll
        for (int w = 0; w < 8; w++) a += sred[w][t];
        g_partials[(size_t)blockIdx.x * 8 + t] = a;
    }
}

// ---------------- stats ----------------
__global__ void k_stats(const float* __restrict__ bnw,
                        const float* __restrict__ bnb,
                        int nblk, int B)
{
    __shared__ float s[256];
    const int t    = threadIdx.x;
    const int stat = t & 7;
    const int g    = t >> 3;   // 32 groups per stat
    float acc = 0.f;
    for (int i = g; i < nblk; i += 32)
        acc += g_partials[(size_t)i * 8 + stat];
    s[t] = acc;
    __syncthreads();
#pragma unroll
    for (int off = 128; off >= 8; off >>= 1) {
        if (t < off) s[t] += s[t + off];
        __syncthreads();
    }
    if (t < 4) {
        float invB = 1.0f / (float)B;
        float mean = s[t] * invB;
        float var  = s[4 + t] * invB - mean * mean;
        float inv  = rsqrtf(var + BN_EPS);
        float sc   = inv * __ldg(bnw + t);
        g_scale[t] = sc;
        g_shift[t] = __ldg(bnb + t) - mean * sc;
    }
}

__global__ void k_norm(float* __restrict__ zout, int B)
{
    int i = blockIdx.x * blockDim.x + threadIdx.x;
    if (i < B) {
        float4 z = ((float4*)zout)[i];
        z.x = z.x * g_scale[0] + g_shift[0];
        z.y = z.y * g_scale[1] + g_shift[1];
        z.z = z.z * g_scale[2] + g_shift[2];
        z.w = z.w * g_scale[3] + g_shift[3];
        ((float4*)zout)[i] = z;
    }
}

extern "C" void kernel_launch(void* const* d_in, const int* in_sizes, int n_in,
                              void* d_out, int out_size)
{
    const float* x     = (const float*)d_in[0];
    const float* enc_w = (const float*)d_in[1];
    const float* enc_b = (const float*)d_in[2];
    const float* qp    = (const float*)d_in[3];
    const float* bnw   = (const float*)d_in[4];
    const float* bnb   = (const float*)d_in[5];
    float* out = (float*)d_out;

    int B     = in_sizes[0] / IMG;   // 131072
    int nblkP = B / SPB;             // 8192
    int nblkC = B / 256;             // 512

    k_pool<<<nblkP, 256>>>(x);
    k_circuit<<<nblkC, 256>>>(enc_w, enc_b, qp, out);
    k_stats<<<1, 256>>>(bnw, bnb, nblkC, B);
    k_norm<<<(B + 255) / 256, 256>>>(out, B);
}

// round 3
// speedup vs baseline: 1.3166x; 1.0794x over previous
#include <cuda_runtime.h>

#define NQ   4
#define IMG  576
#define SS   584      // padded sample stride in smem floats
#define BN_EPS 1e-5f

// static scratch (no allocation)
__device__ float g_partials[1024 * 8];
__device__ float g_scale[4];
__device__ float g_shift[4];

// ---------------- fused pool + circuit + partial-stats ----------------
__global__ void __launch_bounds__(256, 2) k_main(
    const float* __restrict__ x,
    const float* __restrict__ enc_w,   // (4,16)
    const float* __restrict__ enc_b,   // (4,)
    const float* __restrict__ qp,      // (2,4)
    float* __restrict__ zout)          // (B,4)
{
    __shared__ float stage[16 * SS];       // 37376 B
    __shared__ float pr[2][16][17];        // pooled handoff, double buffered
    __shared__ float sred[8][8];

    const int t   = threadIdx.x;
    const int blk = blockIdx.x;
    const float4* xg = (const float4*)(x + (size_t)blk * 256 * IMG);

    float pl[16];   // this thread's pooled features (sample blk*256 + t)

#pragma unroll 1
    for (int r = 0; r < 16; r++) {
        // ---- stage 16 samples (round r), coalesced float4 ----
        const float4* xr = xg + r * 2304;   // 16 samples * 144 float4
#pragma unroll
        for (int k = 0; k < 9; k++) {
            int i4 = t + k * 256;
            int s  = i4 / 144;
            int w  = i4 - s * 144;
            *(float4*)(stage + s * SS + w * 4) = xr[i4];
        }
        __syncthreads();

        // ---- pool: thread t -> (sample t/16, bin t%16) ----
        {
            int s  = t >> 4, b = t & 15;
            int rb = b >> 2, cb = b & 3;
            const float* bp = stage + s * SS + rb * 144 + cb * 6;
            float acc = 0.f;
#pragma unroll
            for (int dr = 0; dr < 6; dr++) {
                const float2* p2 = (const float2*)(bp + dr * 24);
                float2 a = p2[0], c = p2[1], d = p2[2];
                acc += (a.x + a.y) + (c.x + c.y) + (d.x + d.y);
            }
            pr[r & 1][s][b] = acc * (1.0f / 36.0f);
        }
        __syncthreads();

        // ---- owner threads of round r grab their pooled vector ----
        if ((t >> 4) == r) {
#pragma unroll
            for (int i = 0; i < 16; i++) pl[i] = pr[r & 1][t & 15][i];
        }
        // safe: pr[r&1] is only rewritten in round r+2, two barriers away
    }

    // ---- encoder ----
    float enc[NQ];
#pragma unroll
    for (int k = 0; k < NQ; k++) {
        float a = __ldg(enc_b + k);
#pragma unroll
        for (int i = 0; i < 16; i++)
            a += pl[i] * __ldg(enc_w + k * 16 + i);
        enc[k] = a;
    }

    // ---- statevector circuit in registers ----
    float sx[16], sy[16];
#pragma unroll
    for (int i = 0; i < 16; i++) { sx[i] = 0.f; sy[i] = 0.f; }
    sx[0] = 1.f;

#pragma unroll
    for (int layer = 0; layer < 2; layer++) {
#pragma unroll
        for (int q = 0; q < NQ; q++) {
            const int st = 8 >> q;
            float c, sn;
            __sincosf(0.5f * enc[q], &sn, &c);
#pragma unroll
            for (int i = 0; i < 16; i++) {
                if ((i & st) == 0) {
                    const int j = i | st;
                    float ax = sx[i], ay = sy[i];
                    float bx = sx[j], by = sy[j];
                    sx[i] = c * ax - sn * bx;  sy[i] = c * ay - sn * by;
                    sx[j] = sn * ax + c * bx;  sy[j] = sn * ay + c * by;
                }
            }
            float hc, hs;
            __sincosf(0.5f * __ldg(qp + layer * NQ + q), &hs, &hc);
#pragma unroll
            for (int i = 0; i < 16; i++) {
                float xx = sx[i], yy = sy[i];
                if (i & st) { sx[i] = xx * hc - yy * hs;  sy[i] = yy * hc + xx * hs; }
                else        { sx[i] = xx * hc + yy * hs;  sy[i] = yy * hc - xx * hs; }
            }
        }
        // composed CNOT ring permutation (compile-time register rename)
        {
            constexpr int P[16] = {0, 13, 3, 14, 6, 11, 5, 8, 12, 1, 15, 2, 10, 7, 9, 4};
            float tx[16], ty[16];
#pragma unroll
            for (int i = 0; i < 16; i++) { tx[i] = sx[i]; ty[i] = sy[i]; }
#pragma unroll
            for (int i = 0; i < 16; i++) { sx[i] = tx[P[i]]; sy[i] = ty[P[i]]; }
        }
    }

    // ---- Z expectations ----
    float z0 = 0.f, z1 = 0.f, z2 = 0.f, z3 = 0.f;
#pragma unroll
    for (int i = 0; i < 16; i++) {
        float p = sx[i] * sx[i] + sy[i] * sy[i];
        z0 += ((i >> 3) & 1) ? -p : p;
        z1 += ((i >> 2) & 1) ? -p : p;
        z2 += ((i >> 1) & 1) ? -p : p;
        z3 += ( i       & 1) ? -p : p;
    }

    *(float4*)(zout + (size_t)(blk * 256 + t) * 4) = make_float4(z0, z1, z2, z3);

    // ---- deterministic block (sum, sumsq) ----
    float v[8] = {z0, z1, z2, z3, z0 * z0, z1 * z1, z2 * z2, z3 * z3};
#pragma unroll
    for (int off = 16; off >= 1; off >>= 1)
#pragma unroll
        for (int j = 0; j < 8; j++)
            v[j] += __shfl_xor_sync(0xffffffffu, v[j], off);

    const int wid = t >> 5, lid = t & 31;
    if (lid == 0)
#pragma unroll
        for (int j = 0; j < 8; j++) sred[wid][j] = v[j];
    __syncthreads();
    if (t < 8) {
        float a = 0.f;
#pragma unroll
        for (int w = 0; w < 8; w++) a += sred[w][t];
        g_partials[(size_t)blk * 8 + t] = a;
    }
}

// ---------------- stats ----------------
__global__ void k_stats(const float* __restrict__ bnw,
                        const float* __restrict__ bnb,
                        int nblk, int B)
{
    __shared__ float s[256];
    const int t    = threadIdx.x;
    const int stat = t & 7;
    const int g    = t >> 3;
    float acc = 0.f;
    for (int i = g; i < nblk; i += 32)
        acc += g_partials[(size_t)i * 8 + stat];
    s[t] = acc;
    __syncthreads();
#pragma unroll
    for (int off = 128; off >= 8; off >>= 1) {
        if (t < off) s[t] += s[t + off];
        __syncthreads();
    }
    if (t < 4) {
        float invB = 1.0f / (float)B;
        float mean = s[t] * invB;
        float var  = s[4 + t] * invB - mean * mean;
        float inv  = rsqrtf(var + BN_EPS);
        float sc   = inv * __ldg(bnw + t);
        g_scale[t] = sc;
        g_shift[t] = __ldg(bnb + t) - mean * sc;
    }
}

// ---------------- normalize: 4 independent float4 per thread ----------------
__global__ void __launch_bounds__(256) k_norm(float* __restrict__ zout, int n4)
{
    const float4 sc = make_float4(g_scale[0], g_scale[1], g_scale[2], g_scale[3]);
    const float4 sh = make_float4(g_shift[0], g_shift[1], g_shift[2], g_shift[3]);
    const int base   = blockIdx.x * 256 + threadIdx.x;
    const int stride = gridDim.x * 256;

    float4 v[4];
    int idx[4];
#pragma unroll
    for (int k = 0; k < 4; k++) {
        idx[k] = base + k * stride;
        if (idx[k] < n4) v[k] = ((float4*)zout)[idx[k]];
    }
#pragma unroll
    for (int k = 0; k < 4; k++) {
        if (idx[k] < n4) {
            float4 z = v[k];
            z.x = z.x * sc.x + sh.x;
            z.y = z.y * sc.y + sh.y;
            z.z = z.z * sc.z + sh.z;
            z.w = z.w * sc.w + sh.w;
            ((float4*)zout)[idx[k]] = z;
        }
    }
}

extern "C" void kernel_launch(void* const* d_in, const int* in_sizes, int n_in,
                              void* d_out, int out_size)
{
    const float* x     = (const float*)d_in[0];
    const float* enc_w = (const float*)d_in[1];
    const float* enc_b = (const float*)d_in[2];
    const float* qp    = (const float*)d_in[3];
    const float* bnw   = (const float*)d_in[4];
    const float* bnb   = (const float*)d_in[5];
    float* out = (float*)d_out;

    int B    = in_sizes[0] / IMG;   // 131072
    int nblk = B / 256;             // 512

    k_main<<<nblk, 256>>>(x, enc_w, enc_b, qp, out);
    k_stats<<<1, 256>>>(bnw, bnb, nblk, B);
    k_norm<<<128, 256>>>(out, B);
}

// round 4
// speedup vs baseline: 1.5344x; 1.1654x over previous
#include <cuda_runtime.h>
#include <cstdint>

#define NQ     4
#define IMG    576
#define SPR    8            // samples per round
#define ROUNDS 32           // 256 samples per block
#define SS     584          // padded sample stride in smem floats
#define BN_EPS 1e-5f

// static scratch (no allocation)
__device__ float g_partials[1024 * 8];
__device__ float g_scale[4];
__device__ float g_shift[4];

__device__ __forceinline__ void cp_async16(uint32_t smem_addr, const void* gptr) {
    asm volatile("cp.async.cg.shared.global [%0], [%1], 16;\n" :: "r"(smem_addr), "l"(gptr));
}
#define CP_COMMIT() asm volatile("cp.async.commit_group;\n" ::: "memory")
#define CP_WAIT1()  asm volatile("cp.async.wait_group 1;\n" ::: "memory")
#define CP_WAIT0()  asm volatile("cp.async.wait_group 0;\n" ::: "memory")

// ---------------- fused pool + circuit + partial-stats ----------------
__global__ void __launch_bounds__(256, 4) k_main(
    const float* __restrict__ x,
    const float* __restrict__ enc_w,   // (4,16)
    const float* __restrict__ enc_b,   // (4,)
    const float* __restrict__ qp,      // (2,4)
    float* __restrict__ zout)          // (B,4)
{
    __shared__ float stage[2][SPR * SS];   // 2 x 18688 B
    __shared__ float pr[2][SPR][17];       // pooled handoff
    __shared__ float sred[8][8];

    const int t   = threadIdx.x;
    const int blk = blockIdx.x;
    const float4* xg = (const float4*)(x + (size_t)blk * 256 * IMG);

    uint32_t sbase[2];
    sbase[0] = (uint32_t)__cvta_generic_to_shared(&stage[0][0]);
    sbase[1] = (uint32_t)__cvta_generic_to_shared(&stage[1][0]);

    // enc accumulators (folded in-loop by owner threads)
    float enc[NQ];
#pragma unroll
    for (int k = 0; k < NQ; k++) enc[k] = __ldg(enc_b + k);

    // prefetch rounds 0 and 1
#pragma unroll
    for (int j = 0; j < 2; j++) {
        const float4* src = xg + j * (SPR * 144);
#pragma unroll
        for (int k = 0; k < 5; k++) {
            int i4 = t + k * 256;
            if (i4 < SPR * 144) {
                int s = i4 / 144, w = i4 - s * 144;
                cp_async16(sbase[j] + (uint32_t)(s * SS + w * 4) * 4u, src + i4);
            }
        }
        CP_COMMIT();
    }

#pragma unroll 1
    for (int r = 0; r < ROUNDS; r++) {
        if (r == ROUNDS - 1) { CP_WAIT0(); } else { CP_WAIT1(); }
        __syncthreads();

        // ---- pool: threads 0..127 -> (sample t/16, bin t%16) ----
        if (t < 128) {
            int s  = t >> 4, b = t & 15;
            int rb = b >> 2, cb = b & 3;
            const float* bp = &stage[r & 1][0] + s * SS + rb * 144 + cb * 6;
            float acc = 0.f;
#pragma unroll
            for (int dr = 0; dr < 6; dr++) {
                const float2* p2 = (const float2*)(bp + dr * 24);
                float2 a = p2[0], c = p2[1], d = p2[2];
                acc += (a.x + a.y) + (c.x + c.y) + (d.x + d.y);
            }
            pr[r & 1][s][b] = acc * (1.0f / 36.0f);
        }
        __syncthreads();

        // ---- refill freed buffer with round r+2 ----
        if (r + 2 < ROUNDS) {
            const float4* src = xg + (r + 2) * (SPR * 144);
#pragma unroll
            for (int k = 0; k < 5; k++) {
                int i4 = t + k * 256;
                if (i4 < SPR * 144) {
                    int s = i4 / 144, w = i4 - s * 144;
                    cp_async16(sbase[r & 1] + (uint32_t)(s * SS + w * 4) * 4u, src + i4);
                }
            }
        }
        CP_COMMIT();

        // ---- owners of round r fold pooled -> enc (pr safe until round r+2 pool) ----
        if ((t >> 3) == r) {
            const float* pv = pr[r & 1][t & 7];
#pragma unroll
            for (int k = 0; k < NQ; k++) {
                float a = enc[k];
#pragma unroll
                for (int i = 0; i < 16; i++)
                    a += pv[i] * __ldg(enc_w + k * 16 + i);
                enc[k] = a;
            }
        }
    }

    // ---- statevector circuit in registers ----
    float sx[16], sy[16];
#pragma unroll
    for (int i = 0; i < 16; i++) { sx[i] = 0.f; sy[i] = 0.f; }
    sx[0] = 1.f;

#pragma unroll
    for (int layer = 0; layer < 2; layer++) {
#pragma unroll
        for (int q = 0; q < NQ; q++) {
            const int st = 8 >> q;
            float c, sn;
            __sincosf(0.5f * enc[q], &sn, &c);
#pragma unroll
            for (int i = 0; i < 16; i++) {
                if ((i & st) == 0) {
                    const int j = i | st;
                    float ax = sx[i], ay = sy[i];
                    float bx = sx[j], by = sy[j];
                    sx[i] = c * ax - sn * bx;  sy[i] = c * ay - sn * by;
                    sx[j] = sn * ax + c * bx;  sy[j] = sn * ay + c * by;
                }
            }
            float hc, hs;
            __sincosf(0.5f * __ldg(qp + layer * NQ + q), &hs, &hc);
#pragma unroll
            for (int i = 0; i < 16; i++) {
                float xx = sx[i], yy = sy[i];
                if (i & st) { sx[i] = xx * hc - yy * hs;  sy[i] = yy * hc + xx * hs; }
                else        { sx[i] = xx * hc + yy * hs;  sy[i] = yy * hc - xx * hs; }
            }
        }
        {   // composed CNOT ring permutation (register rename)
            constexpr int P[16] = {0, 13, 3, 14, 6, 11, 5, 8, 12, 1, 15, 2, 10, 7, 9, 4};
            float tx[16], ty[16];
#pragma unroll
            for (int i = 0; i < 16; i++) { tx[i] = sx[i]; ty[i] = sy[i]; }
#pragma unroll
            for (int i = 0; i < 16; i++) { sx[i] = tx[P[i]]; sy[i] = ty[P[i]]; }
        }
    }

    // ---- Z expectations ----
    float z0 = 0.f, z1 = 0.f, z2 = 0.f, z3 = 0.f;
#pragma unroll
    for (int i = 0; i < 16; i++) {
        float p = sx[i] * sx[i] + sy[i] * sy[i];
        z0 += ((i >> 3) & 1) ? -p : p;
        z1 += ((i >> 2) & 1) ? -p : p;
        z2 += ((i >> 1) & 1) ? -p : p;
        z3 += ( i       & 1) ? -p : p;
    }

    *(float4*)(zout + (size_t)(blk * 256 + t) * 4) = make_float4(z0, z1, z2, z3);

    // ---- deterministic block (sum, sumsq) ----
    float v[8] = {z0, z1, z2, z3, z0 * z0, z1 * z1, z2 * z2, z3 * z3};
#pragma unroll
    for (int off = 16; off >= 1; off >>= 1)
#pragma unroll
        for (int j = 0; j < 8; j++)
            v[j] += __shfl_xor_sync(0xffffffffu, v[j], off);

    const int wid = t >> 5, lid = t & 31;
    if (lid == 0)
#pragma unroll
        for (int j = 0; j < 8; j++) sred[wid][j] = v[j];
    __syncthreads();
    if (t < 8) {
        float a = 0.f;
#pragma unroll
        for (int w = 0; w < 8; w++) a += sred[w][t];
        g_partials[(size_t)blk * 8 + t] = a;
    }
}

// ---------------- stats ----------------
__global__ void k_stats(const float* __restrict__ bnw,
                        const float* __restrict__ bnb,
                        int nblk, int B)
{
    __shared__ float s[256];
    const int t    = threadIdx.x;
    const int stat = t & 7;
    const int g    = t >> 3;
    float acc = 0.f;
    for (int i = g; i < nblk; i += 32)
        acc += g_partials[(size_t)i * 8 + stat];
    s[t] = acc;
    __syncthreads();
#pragma unroll
    for (int off = 128; off >= 8; off >>= 1) {
        if (t < off) s[t] += s[t + off];
        __syncthreads();
    }
    if (t < 4) {
        float invB = 1.0f / (float)B;
        float mean = s[t] * invB;
        float var  = s[4 + t] * invB - mean * mean;
        float inv  = rsqrtf(var + BN_EPS);
        float sc   = inv * __ldg(bnw + t);
        g_scale[t] = sc;
        g_shift[t] = __ldg(bnb + t) - mean * sc;
    }
}

// ---------------- normalize: 4 independent float4 per thread ----------------
__global__ void __launch_bounds__(256) k_norm(float* __restrict__ zout, int n4)
{
    const float4 sc = make_float4(g_scale[0], g_scale[1], g_scale[2], g_scale[3]);
    const float4 sh = make_float4(g_shift[0], g_shift[1], g_shift[2], g_shift[3]);
    const int base   = blockIdx.x * 256 + threadIdx.x;
    const int stride = gridDim.x * 256;

    float4 v[4];
    int idx[4];
#pragma unroll
    for (int k = 0; k < 4; k++) {
        idx[k] = base + k * stride;
        if (idx[k] < n4) v[k] = ((float4*)zout)[idx[k]];
    }
#pragma unroll
    for (int k = 0; k < 4; k++) {
        if (idx[k] < n4) {
            float4 z = v[k];
            z.x = z.x * sc.x + sh.x;
            z.y = z.y * sc.y + sh.y;
            z.z = z.z * sc.z + sh.z;
            z.w = z.w * sc.w + sh.w;
            ((float4*)zout)[idx[k]] = z;
        }
    }
}

extern "C" void kernel_launch(void* const* d_in, const int* in_sizes, int n_in,
                              void* d_out, int out_size)
{
    const float* x     = (const float*)d_in[0];
    const float* enc_w = (const float*)d_in[1];
    const float* enc_b = (const float*)d_in[2];
    const float* qp    = (const float*)d_in[3];
    const float* bnw   = (const float*)d_in[4];
    const float* bnb   = (const float*)d_in[5];
    float* out = (float*)d_out;

    int B    = in_sizes[0] / IMG;   // 131072
    int nblk = B / 256;             // 512

    k_main<<<nblk, 256>>>(x, enc_w, enc_b, qp, out);
    k_stats<<<1, 256>>>(bnw, bnb, nblk, B);
    k_norm<<<128, 256>>>(out, B);
}